// round 1
// baseline (speedup 1.0000x reference)
#include <cuda_runtime.h>
#include <cstddef>

#define Bn 8
#define Cc 256
#define Nn 4096      // 64*64 spatial
#define Mm 1024      // 32*32 pooled
#define Dd 32
#define Dv 128

// Scratch (device globals; no allocations allowed)
__device__ float g_theta[Bn * Nn * Dd];   // (n, i, d)       4 MB
__device__ float g_phi[Bn * Dd * Mm];     // (n, d, j)       1 MB
__device__ float g_gp [Bn * Dv * Mm];     // (n, v, j)       4 MB
__device__ float g_att[Bn * Nn * Dv];     // (n, i, v)      16 MB

// ---------------------------------------------------------------------------
// Kernel 1: fused projections + maxpool.
// grid (32 i-tiles, 3 groups, 8 batches), 256 threads.
// group 0: theta(32)+phi(32) rows; group 1: g[0:64]; group 2: g[64:128].
// i-tile = 128 contiguous spatial positions = image rows {2*bi, 2*bi+1},
// so each 2x2 maxpool window is entirely inside the tile.
// ---------------------------------------------------------------------------
__global__ void proj_kernel(const float* __restrict__ x,
                            const float* __restrict__ theta_w, const float* __restrict__ theta_b,
                            const float* __restrict__ phi_w,   const float* __restrict__ phi_b,
                            const float* __restrict__ g_w,     const float* __restrict__ g_b)
{
    extern __shared__ float sm[];
    float* Ws = sm;               // 64 x 33
    float* Xs = Ws + 64 * 33;     // 32 x 132
    float* Ys = Xs + 32 * 132;    // 64 x 128

    const int bi  = blockIdx.x;
    const int grp = blockIdx.y;
    const int n   = blockIdx.z;
    const int t   = threadIdx.x;
    const int base = bi * 128;

    const int rg  = t >> 5;         // 0..7 output-row group (8 rows each)
    const int col = (t & 31) * 4;   // 0..124 spatial col

    float acc[8][4];
#pragma unroll
    for (int r = 0; r < 8; r++)
#pragma unroll
        for (int c = 0; c < 4; c++) acc[r][c] = 0.f;

    const float* xb = x + (size_t)n * Cc * Nn;

    for (int kc = 0; kc < Cc; kc += 32) {
        for (int idx = t; idx < 64 * 32; idx += 256) {
            int r = idx >> 5, k = idx & 31;
            float wv;
            if (grp == 0) wv = (r < 32) ? theta_w[r * Cc + kc + k]
                                        : phi_w[(r - 32) * Cc + kc + k];
            else          wv = g_w[((grp - 1) * 64 + r) * Cc + kc + k];
            Ws[r * 33 + k] = wv;
        }
        for (int idx = t; idx < 32 * 128; idx += 256) {
            int k = idx >> 7, i = idx & 127;
            Xs[k * 132 + i] = xb[(size_t)(kc + k) * Nn + base + i];
        }
        __syncthreads();
#pragma unroll
        for (int k = 0; k < 32; k++) {
            float4 xv = *(const float4*)&Xs[k * 132 + col];
#pragma unroll
            for (int r = 0; r < 8; r++) {
                float wv = Ws[(rg * 8 + r) * 33 + k];
                acc[r][0] += wv * xv.x; acc[r][1] += wv * xv.y;
                acc[r][2] += wv * xv.z; acc[r][3] += wv * xv.w;
            }
        }
        __syncthreads();
    }

#pragma unroll
    for (int r = 0; r < 8; r++) {
        int row = rg * 8 + r;
        float b;
        if (grp == 0) b = (row < 32) ? theta_b[row] : phi_b[row - 32];
        else          b = g_b[(grp - 1) * 64 + row];
#pragma unroll
        for (int c = 0; c < 4; c++) Ys[row * 128 + col + c] = acc[r][c] + b;
    }
    __syncthreads();

    if (grp == 0) {
        // theta rows 0..31 -> (n, i, d)
        for (int idx = t; idx < 32 * 128; idx += 256) {
            int o = idx & 31, i = idx >> 5;
            g_theta[((size_t)n * Nn + base + i) * Dd + o] = Ys[o * 128 + i];
        }
        // phi rows 32..63 -> maxpool -> (n, d, j)
        for (int idx = t; idx < 32 * 32; idx += 256) {
            int o = idx >> 5, jw = idx & 31;
            const float* yr = &Ys[(32 + o) * 128];
            float m0 = fmaxf(yr[2 * jw],      yr[2 * jw + 1]);
            float m1 = fmaxf(yr[64 + 2 * jw], yr[64 + 2 * jw + 1]);
            g_phi[((size_t)n * Dd + o) * Mm + bi * 32 + jw] = fmaxf(m0, m1);
        }
    } else {
        int vbase = (grp - 1) * 64;
        for (int idx = t; idx < 64 * 32; idx += 256) {
            int v = idx >> 5, jw = idx & 31;
            const float* yr = &Ys[v * 128];
            float m0 = fmaxf(yr[2 * jw],      yr[2 * jw + 1]);
            float m1 = fmaxf(yr[64 + 2 * jw], yr[64 + 2 * jw + 1]);
            g_gp[((size_t)n * Dv + vbase + v) * Mm + bi * 32 + jw] = fmaxf(m0, m1);
        }
    }
}

// ---------------------------------------------------------------------------
// Kernel 2: flash-style attention. grid (64 q-tiles, 8 batches), 256 threads.
// 64 queries/block, key loop over 8 blocks of 128 keys. Attention matrix
// never hits HBM.
// ---------------------------------------------------------------------------
__global__ void attn_kernel()
{
    extern __shared__ float sm[];
    float* Ts   = sm;                   // 64 x 32
    float* Phs  = Ts  + 64 * 32;        // 32 x 132
    float* Es   = Phs + 32 * 132;       // 64 x 129
    float* Gs   = Es  + 64 * 129;       // 128 x 132  (Gs[k][v])
    float* m_s  = Gs  + 128 * 132;      // 64
    float* l_s  = m_s + 64;             // 64
    float* sc_s = l_s + 64;             // 64

    const int qt = blockIdx.x, n = blockIdx.y;
    const int t  = threadIdx.x;
    const int qg = t >> 5;              // query group 0..7 (8 q each)
    const int vcol = (t & 31) * 4;      // v (and k) column base
    const int qbase = qg * 8;
    const int ibase = qt * 64;

    for (int idx = t; idx < 64 * 32; idx += 256)
        Ts[idx] = g_theta[((size_t)n * Nn + ibase) * Dd + idx];
    if (t < 64) { m_s[t] = -1e30f; l_s[t] = 0.f; }

    float acc[8][4];
#pragma unroll
    for (int r = 0; r < 8; r++)
#pragma unroll
        for (int c = 0; c < 4; c++) acc[r][c] = 0.f;
    __syncthreads();

    for (int kb = 0; kb < 8; kb++) {
        const int jb = kb * 128;
        for (int idx = t; idx < 32 * 128; idx += 256) {
            int d = idx >> 7, j = idx & 127;
            Phs[d * 132 + j] = g_phi[((size_t)n * Dd + d) * Mm + jb + j];
        }
        for (int idx = t; idx < 128 * 32; idx += 256) {
            int v = idx >> 5, j = (idx & 31) * 4;
            float4 gv = *(const float4*)&g_gp[((size_t)n * Dv + v) * Mm + jb + j];
            Gs[(j    ) * 132 + v] = gv.x;
            Gs[(j + 1) * 132 + v] = gv.y;
            Gs[(j + 2) * 132 + v] = gv.z;
            Gs[(j + 3) * 132 + v] = gv.w;
        }
        __syncthreads();

        // energy tile: e[q][k] = theta[q,:] . phi[:,k]
        float e[8][4];
#pragma unroll
        for (int r = 0; r < 8; r++)
#pragma unroll
            for (int c = 0; c < 4; c++) e[r][c] = 0.f;
#pragma unroll
        for (int d = 0; d < 32; d++) {
            float4 ph = *(const float4*)&Phs[d * 132 + vcol];
#pragma unroll
            for (int r = 0; r < 8; r++) {
                float th = Ts[(qbase + r) * 32 + d];
                e[r][0] += th * ph.x; e[r][1] += th * ph.y;
                e[r][2] += th * ph.z; e[r][3] += th * ph.w;
            }
        }
#pragma unroll
        for (int r = 0; r < 8; r++)
#pragma unroll
            for (int c = 0; c < 4; c++)
                Es[(qbase + r) * 129 + vcol + c] = e[r][c];
        __syncthreads();

        // online softmax per query row
        if (t < 64) {
            float* er = &Es[t * 129];
            float mo = m_s[t];
            float rm = mo;
#pragma unroll 4
            for (int k = 0; k < 128; k++) rm = fmaxf(rm, er[k]);
            float sc = __expf(mo - rm);
            float sum = 0.f;
#pragma unroll 4
            for (int k = 0; k < 128; k++) {
                float p = __expf(er[k] - rm);
                er[k] = p; sum += p;
            }
            l_s[t] = l_s[t] * sc + sum;
            m_s[t] = rm;
            sc_s[t] = sc;
        }
        __syncthreads();

#pragma unroll
        for (int r = 0; r < 8; r++) {
            float sc = sc_s[qbase + r];
            acc[r][0] *= sc; acc[r][1] *= sc; acc[r][2] *= sc; acc[r][3] *= sc;
        }
        // P . V
#pragma unroll
        for (int k = 0; k < 128; k++) {
            float4 gv = *(const float4*)&Gs[k * 132 + vcol];
#pragma unroll
            for (int r = 0; r < 8; r++) {
                float p = Es[(qbase + r) * 129 + k];
                acc[r][0] += p * gv.x; acc[r][1] += p * gv.y;
                acc[r][2] += p * gv.z; acc[r][3] += p * gv.w;
            }
        }
        __syncthreads();
    }

#pragma unroll
    for (int r = 0; r < 8; r++) {
        float inv = 1.f / l_s[qbase + r];
        float4 o;
        o.x = acc[r][0] * inv; o.y = acc[r][1] * inv;
        o.z = acc[r][2] * inv; o.w = acc[r][3] * inv;
        *(float4*)&g_att[((size_t)n * Nn + ibase + qbase + r) * Dv + vcol] = o;
    }
}

// ---------------------------------------------------------------------------
// Kernel 3: output 1x1 conv + residual. grid (32 i-blocks, 4 c-blocks, 8).
// out[n,c,i] = gamma*( sum_v W[c,v]*att[n,i,v] + b[c] ) + x[n,c,i]
// ---------------------------------------------------------------------------
__global__ void outconv_kernel(const float* __restrict__ x,
                               const float* __restrict__ out_w,
                               const float* __restrict__ out_b,
                               const float* __restrict__ gamma,
                               float* __restrict__ out)
{
    extern __shared__ float sm[];
    float* As  = sm;               // 128 v x 132 i (transposed att tile)
    float* Wsm = As + 128 * 132;   // 64 c x 128 v

    const int ib = blockIdx.x, cb = blockIdx.y, n = blockIdx.z;
    const int t = threadIdx.x;
    const int ibase = ib * 128, cbase = cb * 64;

    for (int idx = t; idx < 128 * 32; idx += 256) {
        int i = idx >> 5, v = (idx & 31) * 4;
        float4 a = *(const float4*)&g_att[((size_t)n * Nn + ibase + i) * Dv + v];
        As[(v    ) * 132 + i] = a.x;
        As[(v + 1) * 132 + i] = a.y;
        As[(v + 2) * 132 + i] = a.z;
        As[(v + 3) * 132 + i] = a.w;
    }
    for (int idx = t; idx < 64 * 128; idx += 256)
        Wsm[idx] = out_w[(size_t)(cbase + (idx >> 7)) * Dv + (idx & 127)];
    __syncthreads();

    const int cg = t >> 5;             // c group 0..7 (8 c each)
    const int icol = (t & 31) * 4;
    float acc[8][4];
#pragma unroll
    for (int r = 0; r < 8; r++)
#pragma unroll
        for (int c = 0; c < 4; c++) acc[r][c] = 0.f;

#pragma unroll
    for (int v = 0; v < 128; v++) {
        float4 av = *(const float4*)&As[v * 132 + icol];
#pragma unroll
        for (int r = 0; r < 8; r++) {
            float wv = Wsm[(cg * 8 + r) * 128 + v];
            acc[r][0] += wv * av.x; acc[r][1] += wv * av.y;
            acc[r][2] += wv * av.z; acc[r][3] += wv * av.w;
        }
    }

    const float gm = gamma[0];
#pragma unroll
    for (int r = 0; r < 8; r++) {
        int c = cbase + cg * 8 + r;
        float b = out_b[c];
        size_t off = ((size_t)n * Cc + c) * Nn + ibase + icol;
        float4 xv = *(const float4*)&x[off];
        float4 o;
        o.x = gm * (acc[r][0] + b) + xv.x;
        o.y = gm * (acc[r][1] + b) + xv.y;
        o.z = gm * (acc[r][2] + b) + xv.z;
        o.w = gm * (acc[r][3] + b) + xv.w;
        *(float4*)&out[off] = o;
    }
}

// ---------------------------------------------------------------------------
extern "C" void kernel_launch(void* const* d_in, const int* in_sizes, int n_in,
                              void* d_out, int out_size)
{
    const float* x       = (const float*)d_in[0];
    const float* theta_w = (const float*)d_in[1];
    const float* theta_b = (const float*)d_in[2];
    const float* phi_w   = (const float*)d_in[3];
    const float* phi_b   = (const float*)d_in[4];
    const float* g_w     = (const float*)d_in[5];
    const float* g_b     = (const float*)d_in[6];
    const float* out_w   = (const float*)d_in[7];
    const float* out_b   = (const float*)d_in[8];
    const float* gamma   = (const float*)d_in[9];
    float* out = (float*)d_out;

    const int smem1 = (64 * 33 + 32 * 132 + 64 * 128) * 4;                        // ~58 KB
    const int smem2 = (64 * 32 + 32 * 132 + 64 * 129 + 128 * 132 + 192) * 4;      // ~126 KB
    const int smem3 = (128 * 132 + 64 * 128) * 4;                                 // ~100 KB

    cudaFuncSetAttribute(proj_kernel,    cudaFuncAttributeMaxDynamicSharedMemorySize, smem1);
    cudaFuncSetAttribute(attn_kernel,    cudaFuncAttributeMaxDynamicSharedMemorySize, smem2);
    cudaFuncSetAttribute(outconv_kernel, cudaFuncAttributeMaxDynamicSharedMemorySize, smem3);

    proj_kernel<<<dim3(32, 3, Bn), 256, smem1>>>(x, theta_w, theta_b,
                                                 phi_w, phi_b, g_w, g_b);
    attn_kernel<<<dim3(64, Bn), 256, smem2>>>();
    outconv_kernel<<<dim3(32, 4, Bn), 256, smem3>>>(x, out_w, out_b, gamma, out);
}

// round 2
// speedup vs baseline: 2.3438x; 2.3438x over previous
#include <cuda_runtime.h>
#include <cstddef>
#include <cstdint>

#define Bn 8
#define Cc 256
#define Nn 4096      // 64*64 spatial
#define Mm 1024      // 32*32 pooled
#define Dd 32
#define Dv 128

// Scratch (device globals; no allocations allowed)
__device__ float g_theta[Bn * Nn * Dd];   // (n, i, d)
__device__ float g_phi[Bn * Dd * Mm];     // (n, d, j)
__device__ float g_gp [Bn * Dv * Mm];     // (n, v, j)
__device__ float g_att[Bn * Nn * Dv];     // (n, i, v)

__device__ __forceinline__ uint32_t f2tf32(float f) {
    uint32_t r;
    asm("cvt.rna.tf32.f32 %0, %1;" : "=r"(r) : "f"(f));
    return r;
}
__device__ __forceinline__ float tf32r(float f) {
    return __uint_as_float(f2tf32(f));
}
__device__ __forceinline__ void mma_tf32(float c[4], const uint32_t a[4],
                                         uint32_t b0, uint32_t b1) {
    asm volatile("mma.sync.aligned.m16n8k8.row.col.f32.tf32.tf32.f32 "
        "{%0,%1,%2,%3}, {%4,%5,%6,%7}, {%8,%9}, {%0,%1,%2,%3};"
        : "+f"(c[0]), "+f"(c[1]), "+f"(c[2]), "+f"(c[3])
        : "r"(a[0]), "r"(a[1]), "r"(a[2]), "r"(a[3]), "r"(b0), "r"(b1));
}

// ---------------------------------------------------------------------------
// Kernel 1: fused projections + maxpool (scalar, unchanged from R1).
// ---------------------------------------------------------------------------
__global__ void proj_kernel(const float* __restrict__ x,
                            const float* __restrict__ theta_w, const float* __restrict__ theta_b,
                            const float* __restrict__ phi_w,   const float* __restrict__ phi_b,
                            const float* __restrict__ g_w,     const float* __restrict__ g_b)
{
    extern __shared__ float sm[];
    float* Ws = sm;               // 64 x 33
    float* Xs = Ws + 64 * 33;     // 32 x 132
    float* Ys = Xs + 32 * 132;    // 64 x 128

    const int bi  = blockIdx.x;
    const int grp = blockIdx.y;
    const int n   = blockIdx.z;
    const int t   = threadIdx.x;
    const int base = bi * 128;

    const int rg  = t >> 5;
    const int col = (t & 31) * 4;

    float acc[8][4];
#pragma unroll
    for (int r = 0; r < 8; r++)
#pragma unroll
        for (int c = 0; c < 4; c++) acc[r][c] = 0.f;

    const float* xb = x + (size_t)n * Cc * Nn;

    for (int kc = 0; kc < Cc; kc += 32) {
        for (int idx = t; idx < 64 * 32; idx += 256) {
            int r = idx >> 5, k = idx & 31;
            float wv;
            if (grp == 0) wv = (r < 32) ? theta_w[r * Cc + kc + k]
                                        : phi_w[(r - 32) * Cc + kc + k];
            else          wv = g_w[((grp - 1) * 64 + r) * Cc + kc + k];
            Ws[r * 33 + k] = wv;
        }
        for (int idx = t; idx < 32 * 128; idx += 256) {
            int k = idx >> 7, i = idx & 127;
            Xs[k * 132 + i] = xb[(size_t)(kc + k) * Nn + base + i];
        }
        __syncthreads();
#pragma unroll
        for (int k = 0; k < 32; k++) {
            float4 xv = *(const float4*)&Xs[k * 132 + col];
#pragma unroll
            for (int r = 0; r < 8; r++) {
                float wv = Ws[(rg * 8 + r) * 33 + k];
                acc[r][0] += wv * xv.x; acc[r][1] += wv * xv.y;
                acc[r][2] += wv * xv.z; acc[r][3] += wv * xv.w;
            }
        }
        __syncthreads();
    }

#pragma unroll
    for (int r = 0; r < 8; r++) {
        int row = rg * 8 + r;
        float b;
        if (grp == 0) b = (row < 32) ? theta_b[row] : phi_b[row - 32];
        else          b = g_b[(grp - 1) * 64 + row];
#pragma unroll
        for (int c = 0; c < 4; c++) Ys[row * 128 + col + c] = acc[r][c] + b;
    }
    __syncthreads();

    if (grp == 0) {
        for (int idx = t; idx < 32 * 128; idx += 256) {
            int o = idx & 31, i = idx >> 5;
            g_theta[((size_t)n * Nn + base + i) * Dd + o] = Ys[o * 128 + i];
        }
        for (int idx = t; idx < 32 * 32; idx += 256) {
            int o = idx >> 5, jw = idx & 31;
            const float* yr = &Ys[(32 + o) * 128];
            float m0 = fmaxf(yr[2 * jw],      yr[2 * jw + 1]);
            float m1 = fmaxf(yr[64 + 2 * jw], yr[64 + 2 * jw + 1]);
            g_phi[((size_t)n * Dd + o) * Mm + bi * 32 + jw] = fmaxf(m0, m1);
        }
    } else {
        int vbase = (grp - 1) * 64;
        for (int idx = t; idx < 64 * 32; idx += 256) {
            int v = idx >> 5, jw = idx & 31;
            const float* yr = &Ys[v * 128];
            float m0 = fmaxf(yr[2 * jw],      yr[2 * jw + 1]);
            float m1 = fmaxf(yr[64 + 2 * jw], yr[64 + 2 * jw + 1]);
            g_gp[((size_t)n * Dv + vbase + v) * Mm + bi * 32 + jw] = fmaxf(m0, m1);
        }
    }
}

// ---------------------------------------------------------------------------
// Kernel 2: flash attention with tf32 mma.sync.
// grid (32 q-tiles, 8 batches), 256 threads = 8 warps x 16 query rows.
// Key loop: 16 chunks of 64 keys. Q A-fragments live in registers all kernel.
// ---------------------------------------------------------------------------
#define KB  64
#define PHS 72   // phi smem row stride   (banks: d*8+j  -> conflict-free)
#define GSS 68   // g   smem row stride   (banks: v*4+k  -> conflict-free)
#define PSS 72   // P   smem row stride

__global__ void __launch_bounds__(256) attn_mma_kernel()
{
    extern __shared__ float sm[];
    float* Phs = sm;                   // 32  x PHS
    float* Gs  = Phs + Dd * PHS;       // 128 x GSS
    float* Ps  = Gs  + Dv * GSS;       // 128 x PSS

    const int n  = blockIdx.y;
    const int i0 = blockIdx.x * 128;
    const int t  = threadIdx.x;
    const int w  = t >> 5;
    const int lane = t & 31;
    const int qb = w * 16;
    const int gq = lane >> 2;   // group id (row within m16 tile)
    const int tq = lane & 3;    // thread-in-group

    // -------- Q A-fragments (persist all kernel): 4 d-chunks of 8 --------
    uint32_t qa[4][4];
    {
        const float* th = g_theta + ((size_t)n * Nn + i0 + qb) * Dd;
#pragma unroll
        for (int kc = 0; kc < 4; kc++) {
            qa[kc][0] = f2tf32(th[(gq    ) * Dd + kc * 8 + tq    ]);
            qa[kc][1] = f2tf32(th[(gq + 8) * Dd + kc * 8 + tq    ]);
            qa[kc][2] = f2tf32(th[(gq    ) * Dd + kc * 8 + tq + 4]);
            qa[kc][3] = f2tf32(th[(gq + 8) * Dd + kc * 8 + tq + 4]);
        }
    }

    float oacc[16][4];
#pragma unroll
    for (int vt = 0; vt < 16; vt++)
#pragma unroll
        for (int c = 0; c < 4; c++) oacc[vt][c] = 0.f;

    float m0 = -1e30f, m1 = -1e30f, l0 = 0.f, l1 = 0.f;

    for (int kb = 0; kb < Mm / KB; kb++) {
        const int jb = kb * KB;
        __syncthreads();   // previous iteration's Gs/Phs reads complete

        // ---- load phi chunk [32][64], tf32-rounded ----
#pragma unroll
        for (int it = 0; it < 2; it++) {
            int idx = t + it * 256;                 // 512 float4 total
            int d = idx >> 4, j4 = (idx & 15) * 4;
            float4 v = *(const float4*)&g_phi[((size_t)n * Dd + d) * Mm + jb + j4];
            Phs[d * PHS + j4 + 0] = tf32r(v.x);
            Phs[d * PHS + j4 + 1] = tf32r(v.y);
            Phs[d * PHS + j4 + 2] = tf32r(v.z);
            Phs[d * PHS + j4 + 3] = tf32r(v.w);
        }
        // ---- load g chunk [128][64], tf32-rounded ----
#pragma unroll
        for (int it = 0; it < 8; it++) {
            int idx = t + it * 256;                 // 2048 float4 total
            int vv = idx >> 4, j4 = (idx & 15) * 4;
            float4 gv = *(const float4*)&g_gp[((size_t)n * Dv + vv) * Mm + jb + j4];
            Gs[vv * GSS + j4 + 0] = tf32r(gv.x);
            Gs[vv * GSS + j4 + 1] = tf32r(gv.y);
            Gs[vv * GSS + j4 + 2] = tf32r(gv.z);
            Gs[vv * GSS + j4 + 3] = tf32r(gv.w);
        }
        __syncthreads();

        // ---- energy: E[16q x 64k] per warp ----
        float e[8][4];
#pragma unroll
        for (int nt = 0; nt < 8; nt++)
#pragma unroll
            for (int c = 0; c < 4; c++) e[nt][c] = 0.f;
#pragma unroll
        for (int kc = 0; kc < 4; kc++)
#pragma unroll
            for (int nt = 0; nt < 8; nt++) {
                uint32_t b0 = __float_as_uint(Phs[(kc * 8 + tq    ) * PHS + nt * 8 + gq]);
                uint32_t b1 = __float_as_uint(Phs[(kc * 8 + tq + 4) * PHS + nt * 8 + gq]);
                mma_tf32(e[nt], qa[kc], b0, b1);
            }

        // ---- online softmax (rows gq, gq+8 of this warp's 16) ----
        float rm0 = m0, rm1 = m1;
#pragma unroll
        for (int nt = 0; nt < 8; nt++) {
            rm0 = fmaxf(rm0, fmaxf(e[nt][0], e[nt][1]));
            rm1 = fmaxf(rm1, fmaxf(e[nt][2], e[nt][3]));
        }
        rm0 = fmaxf(rm0, __shfl_xor_sync(0xffffffff, rm0, 1));
        rm0 = fmaxf(rm0, __shfl_xor_sync(0xffffffff, rm0, 2));
        rm1 = fmaxf(rm1, __shfl_xor_sync(0xffffffff, rm1, 1));
        rm1 = fmaxf(rm1, __shfl_xor_sync(0xffffffff, rm1, 2));
        float sc0 = __expf(m0 - rm0);
        float sc1 = __expf(m1 - rm1);
        m0 = rm0; m1 = rm1;

        float s0 = 0.f, s1 = 0.f;
#pragma unroll
        for (int nt = 0; nt < 8; nt++) {
            float p0 = __expf(e[nt][0] - rm0);
            float p1 = __expf(e[nt][1] - rm0);
            float p2 = __expf(e[nt][2] - rm1);
            float p3 = __expf(e[nt][3] - rm1);
            s0 += p0 + p1;  s1 += p2 + p3;
            float2 lo = make_float2(tf32r(p0), tf32r(p1));
            float2 hi = make_float2(tf32r(p2), tf32r(p3));
            *(float2*)&Ps[(qb + gq    ) * PSS + nt * 8 + tq * 2] = lo;
            *(float2*)&Ps[(qb + gq + 8) * PSS + nt * 8 + tq * 2] = hi;
        }
        s0 += __shfl_xor_sync(0xffffffff, s0, 1);
        s0 += __shfl_xor_sync(0xffffffff, s0, 2);
        s1 += __shfl_xor_sync(0xffffffff, s1, 1);
        s1 += __shfl_xor_sync(0xffffffff, s1, 2);
        l0 = l0 * sc0 + s0;
        l1 = l1 * sc1 + s1;

        // rescale running output
#pragma unroll
        for (int vt = 0; vt < 16; vt++) {
            oacc[vt][0] *= sc0; oacc[vt][1] *= sc0;
            oacc[vt][2] *= sc1; oacc[vt][3] *= sc1;
        }

        __syncwarp();  // P rows of this warp visible to this warp

        // ---- P.V: O[16q x 128v] += P[16q x 64k] * Gt[64k x 128v] ----
        uint32_t pa[8][4];
#pragma unroll
        for (int kc = 0; kc < 8; kc++) {
            pa[kc][0] = __float_as_uint(Ps[(qb + gq    ) * PSS + kc * 8 + tq    ]);
            pa[kc][1] = __float_as_uint(Ps[(qb + gq + 8) * PSS + kc * 8 + tq    ]);
            pa[kc][2] = __float_as_uint(Ps[(qb + gq    ) * PSS + kc * 8 + tq + 4]);
            pa[kc][3] = __float_as_uint(Ps[(qb + gq + 8) * PSS + kc * 8 + tq + 4]);
        }
#pragma unroll
        for (int vt = 0; vt < 16; vt++)
#pragma unroll
            for (int kc = 0; kc < 8; kc++) {
                uint32_t b0 = __float_as_uint(Gs[(vt * 8 + gq) * GSS + kc * 8 + tq    ]);
                uint32_t b1 = __float_as_uint(Gs[(vt * 8 + gq) * GSS + kc * 8 + tq + 4]);
                mma_tf32(oacc[vt], pa[kc], b0, b1);
            }
    }

    // ---- epilogue: normalize and store (n, i, v) ----
    const float inv0 = 1.f / l0;
    const float inv1 = 1.f / l1;
    float* outp0 = g_att + ((size_t)n * Nn + i0 + qb + gq    ) * Dv;
    float* outp1 = g_att + ((size_t)n * Nn + i0 + qb + gq + 8) * Dv;
#pragma unroll
    for (int vt = 0; vt < 16; vt++) {
        *(float2*)&outp0[vt * 8 + tq * 2] = make_float2(oacc[vt][0] * inv0, oacc[vt][1] * inv0);
        *(float2*)&outp1[vt * 8 + tq * 2] = make_float2(oacc[vt][2] * inv1, oacc[vt][3] * inv1);
    }
}

// ---------------------------------------------------------------------------
// Kernel 3: output 1x1 conv + residual (scalar, unchanged from R1).
// ---------------------------------------------------------------------------
__global__ void outconv_kernel(const float* __restrict__ x,
                               const float* __restrict__ out_w,
                               const float* __restrict__ out_b,
                               const float* __restrict__ gamma,
                               float* __restrict__ out)
{
    extern __shared__ float sm[];
    float* As  = sm;               // 128 v x 132 i
    float* Wsm = As + 128 * 132;   // 64 c x 128 v

    const int ib = blockIdx.x, cb = blockIdx.y, n = blockIdx.z;
    const int t = threadIdx.x;
    const int ibase = ib * 128, cbase = cb * 64;

    for (int idx = t; idx < 128 * 32; idx += 256) {
        int i = idx >> 5, v = (idx & 31) * 4;
        float4 a = *(const float4*)&g_att[((size_t)n * Nn + ibase + i) * Dv + v];
        As[(v    ) * 132 + i] = a.x;
        As[(v + 1) * 132 + i] = a.y;
        As[(v + 2) * 132 + i] = a.z;
        As[(v + 3) * 132 + i] = a.w;
    }
    for (int idx = t; idx < 64 * 128; idx += 256)
        Wsm[idx] = out_w[(size_t)(cbase + (idx >> 7)) * Dv + (idx & 127)];
    __syncthreads();

    const int cg = t >> 5;
    const int icol = (t & 31) * 4;
    float acc[8][4];
#pragma unroll
    for (int r = 0; r < 8; r++)
#pragma unroll
        for (int c = 0; c < 4; c++) acc[r][c] = 0.f;

#pragma unroll
    for (int v = 0; v < 128; v++) {
        float4 av = *(const float4*)&As[v * 132 + icol];
#pragma unroll
        for (int r = 0; r < 8; r++) {
            float wv = Wsm[(cg * 8 + r) * 128 + v];
            acc[r][0] += wv * av.x; acc[r][1] += wv * av.y;
            acc[r][2] += wv * av.z; acc[r][3] += wv * av.w;
        }
    }

    const float gm = gamma[0];
#pragma unroll
    for (int r = 0; r < 8; r++) {
        int c = cbase + cg * 8 + r;
        float b = out_b[c];
        size_t off = ((size_t)n * Cc + c) * Nn + ibase + icol;
        float4 xv = *(const float4*)&x[off];
        float4 o;
        o.x = gm * (acc[r][0] + b) + xv.x;
        o.y = gm * (acc[r][1] + b) + xv.y;
        o.z = gm * (acc[r][2] + b) + xv.z;
        o.w = gm * (acc[r][3] + b) + xv.w;
        *(float4*)&out[off] = o;
    }
}

// ---------------------------------------------------------------------------
extern "C" void kernel_launch(void* const* d_in, const int* in_sizes, int n_in,
                              void* d_out, int out_size)
{
    const float* x       = (const float*)d_in[0];
    const float* theta_w = (const float*)d_in[1];
    const float* theta_b = (const float*)d_in[2];
    const float* phi_w   = (const float*)d_in[3];
    const float* phi_b   = (const float*)d_in[4];
    const float* g_w     = (const float*)d_in[5];
    const float* g_b     = (const float*)d_in[6];
    const float* out_w   = (const float*)d_in[7];
    const float* out_b   = (const float*)d_in[8];
    const float* gamma   = (const float*)d_in[9];
    float* out = (float*)d_out;

    const int smem1 = (64 * 33 + 32 * 132 + 64 * 128) * 4;
    const int smem2 = (Dd * PHS + Dv * GSS + 128 * PSS) * 4;   // ~79 KB
    const int smem3 = (128 * 132 + 64 * 128) * 4;

    cudaFuncSetAttribute(proj_kernel,     cudaFuncAttributeMaxDynamicSharedMemorySize, smem1);
    cudaFuncSetAttribute(attn_mma_kernel, cudaFuncAttributeMaxDynamicSharedMemorySize, smem2);
    cudaFuncSetAttribute(outconv_kernel,  cudaFuncAttributeMaxDynamicSharedMemorySize, smem3);

    proj_kernel<<<dim3(32, 3, Bn), 256, smem1>>>(x, theta_w, theta_b,
                                                 phi_w, phi_b, g_w, g_b);
    attn_mma_kernel<<<dim3(32, Bn), 256, smem2>>>();
    outconv_kernel<<<dim3(32, 4, Bn), 256, smem3>>>(x, out_w, out_b, gamma, out);
}

// round 3
// speedup vs baseline: 2.7395x; 1.1688x over previous
#include <cuda_runtime.h>
#include <cstddef>
#include <cstdint>

#define Bn 8
#define Cc 256
#define Nn 4096      // 64*64 spatial
#define Mm 1024      // 32*32 pooled
#define Dd 32
#define Dv 128

// Scratch (device globals; no allocations allowed)
__device__ float g_theta[Bn * Nn * Dd];   // (n, i, d)
__device__ float g_phi[Bn * Dd * Mm];     // (n, d, j)
__device__ float g_gp [Bn * Dv * Mm];     // (n, v, j)
__device__ float g_att[Bn * Nn * Dv];     // (n, i, v)

__device__ __forceinline__ uint32_t f2tf32(float f) {
    uint32_t r;
    asm("cvt.rna.tf32.f32 %0, %1;" : "=r"(r) : "f"(f));
    return r;
}
__device__ __forceinline__ float tf32r(float f) {
    return __uint_as_float(f2tf32(f));
}
__device__ __forceinline__ void mma_tf32(float c[4], const uint32_t a[4],
                                         uint32_t b0, uint32_t b1) {
    asm volatile("mma.sync.aligned.m16n8k8.row.col.f32.tf32.tf32.f32 "
        "{%0,%1,%2,%3}, {%4,%5,%6,%7}, {%8,%9}, {%0,%1,%2,%3};"
        : "+f"(c[0]), "+f"(c[1]), "+f"(c[2]), "+f"(c[3])
        : "r"(a[0]), "r"(a[1]), "r"(a[2]), "r"(a[3]), "r"(b0), "r"(b1));
}

// ---------------------------------------------------------------------------
// Kernel 1: fused projections + maxpool, tf32 MMA.
// grid (32 i-tiles, 3 groups, 8 batches), 256 threads = 8 warps (4 m x 2 n).
// Block tile: 64 out-channels x 128 spatial, K=256 in 8 chunks of 32.
// ---------------------------------------------------------------------------
#define WS  36    // weight smem stride: bank = 4*gq + tq  (conflict-free)
#define XSS 136   // X smem stride:      bank = 8*tq + gq  (conflict-free)
#define YSS 132

__global__ void __launch_bounds__(256) proj_mma_kernel(
    const float* __restrict__ x,
    const float* __restrict__ theta_w, const float* __restrict__ theta_b,
    const float* __restrict__ phi_w,   const float* __restrict__ phi_b,
    const float* __restrict__ g_w,     const float* __restrict__ g_b)
{
    extern __shared__ float sm[];
    float* Ws = sm;               // 64 x 36
    float* Xs = Ws + 64 * WS;     // 32 x 136
    float* Ys = Xs + 32 * XSS;    // 64 x 132

    const int bi  = blockIdx.x;
    const int grp = blockIdx.y;
    const int n   = blockIdx.z;
    const int t   = threadIdx.x;
    const int w   = t >> 5, lane = t & 31;
    const int gq  = lane >> 2, tq = lane & 3;
    const int mrow = (w & 3) * 16;
    const int nc0  = (w >> 2) * 64;
    const int base = bi * 128;

    float acc[8][4];
#pragma unroll
    for (int nt = 0; nt < 8; nt++)
#pragma unroll
        for (int c = 0; c < 4; c++) acc[nt][c] = 0.f;

    const float* xb = x + (size_t)n * Cc * Nn;

    for (int kc = 0; kc < Cc; kc += 32) {
        for (int idx = t; idx < 64 * 32; idx += 256) {
            int r = idx >> 5, k = idx & 31;
            float wv;
            if (grp == 0) wv = (r < 32) ? theta_w[r * Cc + kc + k]
                                        : phi_w[(r - 32) * Cc + kc + k];
            else          wv = g_w[((grp - 1) * 64 + r) * Cc + kc + k];
            Ws[r * WS + k] = tf32r(wv);
        }
#pragma unroll
        for (int it = 0; it < 4; it++) {
            int idx = t + it * 256;            // 1024 float4
            int k = idx >> 5, i4 = (idx & 31) * 4;
            float4 v = *(const float4*)&xb[(size_t)(kc + k) * Nn + base + i4];
            Xs[k * XSS + i4 + 0] = tf32r(v.x);
            Xs[k * XSS + i4 + 1] = tf32r(v.y);
            Xs[k * XSS + i4 + 2] = tf32r(v.z);
            Xs[k * XSS + i4 + 3] = tf32r(v.w);
        }
        __syncthreads();
#pragma unroll
        for (int ks = 0; ks < 4; ks++) {
            uint32_t a[4];
            a[0] = __float_as_uint(Ws[(mrow + gq    ) * WS + ks * 8 + tq    ]);
            a[1] = __float_as_uint(Ws[(mrow + gq + 8) * WS + ks * 8 + tq    ]);
            a[2] = __float_as_uint(Ws[(mrow + gq    ) * WS + ks * 8 + tq + 4]);
            a[3] = __float_as_uint(Ws[(mrow + gq + 8) * WS + ks * 8 + tq + 4]);
#pragma unroll
            for (int nt = 0; nt < 8; nt++) {
                uint32_t b0 = __float_as_uint(Xs[(ks * 8 + tq    ) * XSS + nc0 + nt * 8 + gq]);
                uint32_t b1 = __float_as_uint(Xs[(ks * 8 + tq + 4) * XSS + nc0 + nt * 8 + gq]);
                mma_tf32(acc[nt], a, b0, b1);
            }
        }
        __syncthreads();
    }

    // stage to Ys with bias
    {
        int r0 = mrow + gq, r1 = mrow + gq + 8;
        float b0, b1;
        if (grp == 0) {
            b0 = (r0 < 32) ? theta_b[r0] : phi_b[r0 - 32];
            b1 = (r1 < 32) ? theta_b[r1] : phi_b[r1 - 32];
        } else {
            b0 = g_b[(grp - 1) * 64 + r0];
            b1 = g_b[(grp - 1) * 64 + r1];
        }
#pragma unroll
        for (int nt = 0; nt < 8; nt++) {
            int col = nc0 + nt * 8 + tq * 2;
            *(float2*)&Ys[r0 * YSS + col] = make_float2(acc[nt][0] + b0, acc[nt][1] + b0);
            *(float2*)&Ys[r1 * YSS + col] = make_float2(acc[nt][2] + b1, acc[nt][3] + b1);
        }
    }
    __syncthreads();

    if (grp == 0) {
        // theta rows 0..31 -> (n, i, d)
        for (int idx = t; idx < 32 * 128; idx += 256) {
            int o = idx & 31, i = idx >> 5;
            g_theta[((size_t)n * Nn + base + i) * Dd + o] = Ys[o * YSS + i];
        }
        // phi rows 32..63 -> maxpool -> (n, d, j)
        for (int idx = t; idx < 32 * 32; idx += 256) {
            int o = idx >> 5, jw = idx & 31;
            const float* yr = &Ys[(32 + o) * YSS];
            float m0 = fmaxf(yr[2 * jw],      yr[2 * jw + 1]);
            float m1 = fmaxf(yr[64 + 2 * jw], yr[64 + 2 * jw + 1]);
            g_phi[((size_t)n * Dd + o) * Mm + bi * 32 + jw] = fmaxf(m0, m1);
        }
    } else {
        int vbase = (grp - 1) * 64;
        for (int idx = t; idx < 64 * 32; idx += 256) {
            int v = idx >> 5, jw = idx & 31;
            const float* yr = &Ys[v * YSS];
            float m0 = fmaxf(yr[2 * jw],      yr[2 * jw + 1]);
            float m1 = fmaxf(yr[64 + 2 * jw], yr[64 + 2 * jw + 1]);
            g_gp[((size_t)n * Dv + vbase + v) * Mm + bi * 32 + jw] = fmaxf(m0, m1);
        }
    }
}

// ---------------------------------------------------------------------------
// Kernel 2: flash attention with tf32 mma.sync (unchanged from R2).
// ---------------------------------------------------------------------------
#define KB  64
#define PHS 72
#define GSS 68
#define PSS 72

__global__ void __launch_bounds__(256) attn_mma_kernel()
{
    extern __shared__ float sm[];
    float* Phs = sm;                   // 32  x PHS
    float* Gs  = Phs + Dd * PHS;       // 128 x GSS
    float* Ps  = Gs  + Dv * GSS;       // 128 x PSS

    const int n  = blockIdx.y;
    const int i0 = blockIdx.x * 128;
    const int t  = threadIdx.x;
    const int w  = t >> 5;
    const int lane = t & 31;
    const int qb = w * 16;
    const int gq = lane >> 2;
    const int tq = lane & 3;

    uint32_t qa[4][4];
    {
        const float* th = g_theta + ((size_t)n * Nn + i0 + qb) * Dd;
#pragma unroll
        for (int kc = 0; kc < 4; kc++) {
            qa[kc][0] = f2tf32(th[(gq    ) * Dd + kc * 8 + tq    ]);
            qa[kc][1] = f2tf32(th[(gq + 8) * Dd + kc * 8 + tq    ]);
            qa[kc][2] = f2tf32(th[(gq    ) * Dd + kc * 8 + tq + 4]);
            qa[kc][3] = f2tf32(th[(gq + 8) * Dd + kc * 8 + tq + 4]);
        }
    }

    float oacc[16][4];
#pragma unroll
    for (int vt = 0; vt < 16; vt++)
#pragma unroll
        for (int c = 0; c < 4; c++) oacc[vt][c] = 0.f;

    float m0 = -1e30f, m1 = -1e30f, l0 = 0.f, l1 = 0.f;

    for (int kb = 0; kb < Mm / KB; kb++) {
        const int jb = kb * KB;
        __syncthreads();

#pragma unroll
        for (int it = 0; it < 2; it++) {
            int idx = t + it * 256;
            int d = idx >> 4, j4 = (idx & 15) * 4;
            float4 v = *(const float4*)&g_phi[((size_t)n * Dd + d) * Mm + jb + j4];
            Phs[d * PHS + j4 + 0] = tf32r(v.x);
            Phs[d * PHS + j4 + 1] = tf32r(v.y);
            Phs[d * PHS + j4 + 2] = tf32r(v.z);
            Phs[d * PHS + j4 + 3] = tf32r(v.w);
        }
#pragma unroll
        for (int it = 0; it < 8; it++) {
            int idx = t + it * 256;
            int vv = idx >> 4, j4 = (idx & 15) * 4;
            float4 gv = *(const float4*)&g_gp[((size_t)n * Dv + vv) * Mm + jb + j4];
            Gs[vv * GSS + j4 + 0] = tf32r(gv.x);
            Gs[vv * GSS + j4 + 1] = tf32r(gv.y);
            Gs[vv * GSS + j4 + 2] = tf32r(gv.z);
            Gs[vv * GSS + j4 + 3] = tf32r(gv.w);
        }
        __syncthreads();

        float e[8][4];
#pragma unroll
        for (int nt = 0; nt < 8; nt++)
#pragma unroll
            for (int c = 0; c < 4; c++) e[nt][c] = 0.f;
#pragma unroll
        for (int kc = 0; kc < 4; kc++)
#pragma unroll
            for (int nt = 0; nt < 8; nt++) {
                uint32_t b0 = __float_as_uint(Phs[(kc * 8 + tq    ) * PHS + nt * 8 + gq]);
                uint32_t b1 = __float_as_uint(Phs[(kc * 8 + tq + 4) * PHS + nt * 8 + gq]);
                mma_tf32(e[nt], qa[kc], b0, b1);
            }

        float rm0 = m0, rm1 = m1;
#pragma unroll
        for (int nt = 0; nt < 8; nt++) {
            rm0 = fmaxf(rm0, fmaxf(e[nt][0], e[nt][1]));
            rm1 = fmaxf(rm1, fmaxf(e[nt][2], e[nt][3]));
        }
        rm0 = fmaxf(rm0, __shfl_xor_sync(0xffffffff, rm0, 1));
        rm0 = fmaxf(rm0, __shfl_xor_sync(0xffffffff, rm0, 2));
        rm1 = fmaxf(rm1, __shfl_xor_sync(0xffffffff, rm1, 1));
        rm1 = fmaxf(rm1, __shfl_xor_sync(0xffffffff, rm1, 2));
        float sc0 = __expf(m0 - rm0);
        float sc1 = __expf(m1 - rm1);
        m0 = rm0; m1 = rm1;

        float s0 = 0.f, s1 = 0.f;
#pragma unroll
        for (int nt = 0; nt < 8; nt++) {
            float p0 = __expf(e[nt][0] - rm0);
            float p1 = __expf(e[nt][1] - rm0);
            float p2 = __expf(e[nt][2] - rm1);
            float p3 = __expf(e[nt][3] - rm1);
            s0 += p0 + p1;  s1 += p2 + p3;
            float2 lo = make_float2(tf32r(p0), tf32r(p1));
            float2 hi = make_float2(tf32r(p2), tf32r(p3));
            *(float2*)&Ps[(qb + gq    ) * PSS + nt * 8 + tq * 2] = lo;
            *(float2*)&Ps[(qb + gq + 8) * PSS + nt * 8 + tq * 2] = hi;
        }
        s0 += __shfl_xor_sync(0xffffffff, s0, 1);
        s0 += __shfl_xor_sync(0xffffffff, s0, 2);
        s1 += __shfl_xor_sync(0xffffffff, s1, 1);
        s1 += __shfl_xor_sync(0xffffffff, s1, 2);
        l0 = l0 * sc0 + s0;
        l1 = l1 * sc1 + s1;

#pragma unroll
        for (int vt = 0; vt < 16; vt++) {
            oacc[vt][0] *= sc0; oacc[vt][1] *= sc0;
            oacc[vt][2] *= sc1; oacc[vt][3] *= sc1;
        }

        __syncwarp();

        uint32_t pa[8][4];
#pragma unroll
        for (int kc = 0; kc < 8; kc++) {
            pa[kc][0] = __float_as_uint(Ps[(qb + gq    ) * PSS + kc * 8 + tq    ]);
            pa[kc][1] = __float_as_uint(Ps[(qb + gq + 8) * PSS + kc * 8 + tq    ]);
            pa[kc][2] = __float_as_uint(Ps[(qb + gq    ) * PSS + kc * 8 + tq + 4]);
            pa[kc][3] = __float_as_uint(Ps[(qb + gq + 8) * PSS + kc * 8 + tq + 4]);
        }
#pragma unroll
        for (int vt = 0; vt < 16; vt++)
#pragma unroll
            for (int kc = 0; kc < 8; kc++) {
                uint32_t b0 = __float_as_uint(Gs[(vt * 8 + gq) * GSS + kc * 8 + tq    ]);
                uint32_t b1 = __float_as_uint(Gs[(vt * 8 + gq) * GSS + kc * 8 + tq + 4]);
                mma_tf32(oacc[vt], pa[kc], b0, b1);
            }
    }

    const float inv0 = 1.f / l0;
    const float inv1 = 1.f / l1;
    float* outp0 = g_att + ((size_t)n * Nn + i0 + qb + gq    ) * Dv;
    float* outp1 = g_att + ((size_t)n * Nn + i0 + qb + gq + 8) * Dv;
#pragma unroll
    for (int vt = 0; vt < 16; vt++) {
        *(float2*)&outp0[vt * 8 + tq * 2] = make_float2(oacc[vt][0] * inv0, oacc[vt][1] * inv0);
        *(float2*)&outp1[vt * 8 + tq * 2] = make_float2(oacc[vt][2] * inv1, oacc[vt][3] * inv1);
    }
}

// ---------------------------------------------------------------------------
// Kernel 3: output 1x1 conv + residual, tf32 MMA.
// grid (32 i-blocks, 4 c-blocks, 8 batches), 256 threads = 8 warps (4m x 2n).
// Block tile: 64 c x 128 i, K = Dv = 128.
// ---------------------------------------------------------------------------
#define ASS 136   // att smem stride (B frag: bank = 8*tq + gq)
#define OWS 132   // weight smem stride (A frag: bank = 4*gq + tq)

__global__ void __launch_bounds__(256) outconv_mma_kernel(
    const float* __restrict__ x,
    const float* __restrict__ out_w,
    const float* __restrict__ out_b,
    const float* __restrict__ gamma,
    float* __restrict__ out)
{
    extern __shared__ float sm[];
    float* As  = sm;               // 128 v x 136 i  (transposed att tile)
    float* Wsm = As + 128 * ASS;   // 64 c x 132 v

    const int ib = blockIdx.x, cb = blockIdx.y, n = blockIdx.z;
    const int t = threadIdx.x;
    const int w = t >> 5, lane = t & 31;
    const int gq = lane >> 2, tq = lane & 3;
    const int mrow = (w & 3) * 16;
    const int nc0  = (w >> 2) * 64;
    const int ibase = ib * 128, cbase = cb * 64;

    for (int idx = t; idx < 128 * 32; idx += 256) {
        int i = idx >> 5, v = (idx & 31) * 4;
        float4 a = *(const float4*)&g_att[((size_t)n * Nn + ibase + i) * Dv + v];
        As[(v    ) * ASS + i] = tf32r(a.x);
        As[(v + 1) * ASS + i] = tf32r(a.y);
        As[(v + 2) * ASS + i] = tf32r(a.z);
        As[(v + 3) * ASS + i] = tf32r(a.w);
    }
    for (int idx = t; idx < 64 * 128; idx += 256)
        Wsm[(idx >> 7) * OWS + (idx & 127)] =
            tf32r(out_w[(size_t)(cbase + (idx >> 7)) * Dv + (idx & 127)]);
    __syncthreads();

    float acc[8][4];
#pragma unroll
    for (int nt = 0; nt < 8; nt++)
#pragma unroll
        for (int c = 0; c < 4; c++) acc[nt][c] = 0.f;

#pragma unroll
    for (int kc = 0; kc < 16; kc++) {
        uint32_t a[4];
        a[0] = __float_as_uint(Wsm[(mrow + gq    ) * OWS + kc * 8 + tq    ]);
        a[1] = __float_as_uint(Wsm[(mrow + gq + 8) * OWS + kc * 8 + tq    ]);
        a[2] = __float_as_uint(Wsm[(mrow + gq    ) * OWS + kc * 8 + tq + 4]);
        a[3] = __float_as_uint(Wsm[(mrow + gq + 8) * OWS + kc * 8 + tq + 4]);
#pragma unroll
        for (int nt = 0; nt < 8; nt++) {
            uint32_t b0 = __float_as_uint(As[(kc * 8 + tq    ) * ASS + nc0 + nt * 8 + gq]);
            uint32_t b1 = __float_as_uint(As[(kc * 8 + tq + 4) * ASS + nc0 + nt * 8 + gq]);
            mma_tf32(acc[nt], a, b0, b1);
        }
    }

    const float gm = gamma[0];
    const int c0 = cbase + mrow + gq;
    const int c1 = c0 + 8;
    const float b0 = out_b[c0], b1 = out_b[c1];
#pragma unroll
    for (int nt = 0; nt < 8; nt++) {
        int col = ibase + nc0 + nt * 8 + tq * 2;
        size_t off0 = ((size_t)n * Cc + c0) * Nn + col;
        size_t off1 = ((size_t)n * Cc + c1) * Nn + col;
        float2 xv0 = *(const float2*)&x[off0];
        float2 xv1 = *(const float2*)&x[off1];
        float2 o0, o1;
        o0.x = gm * (acc[nt][0] + b0) + xv0.x;
        o0.y = gm * (acc[nt][1] + b0) + xv0.y;
        o1.x = gm * (acc[nt][2] + b1) + xv1.x;
        o1.y = gm * (acc[nt][3] + b1) + xv1.y;
        *(float2*)&out[off0] = o0;
        *(float2*)&out[off1] = o1;
    }
}

// ---------------------------------------------------------------------------
extern "C" void kernel_launch(void* const* d_in, const int* in_sizes, int n_in,
                              void* d_out, int out_size)
{
    const float* x       = (const float*)d_in[0];
    const float* theta_w = (const float*)d_in[1];
    const float* theta_b = (const float*)d_in[2];
    const float* phi_w   = (const float*)d_in[3];
    const float* phi_b   = (const float*)d_in[4];
    const float* g_w     = (const float*)d_in[5];
    const float* g_b     = (const float*)d_in[6];
    const float* out_w   = (const float*)d_in[7];
    const float* out_b   = (const float*)d_in[8];
    const float* gamma   = (const float*)d_in[9];
    float* out = (float*)d_out;

    const int smem1 = (64 * WS + 32 * XSS + 64 * YSS) * 4;       // ~60 KB
    const int smem2 = (Dd * PHS + Dv * GSS + 128 * PSS) * 4;     // ~79 KB
    const int smem3 = (128 * ASS + 64 * OWS) * 4;                // ~103 KB

    cudaFuncSetAttribute(proj_mma_kernel,    cudaFuncAttributeMaxDynamicSharedMemorySize, smem1);
    cudaFuncSetAttribute(attn_mma_kernel,    cudaFuncAttributeMaxDynamicSharedMemorySize, smem2);
    cudaFuncSetAttribute(outconv_mma_kernel, cudaFuncAttributeMaxDynamicSharedMemorySize, smem3);

    proj_mma_kernel<<<dim3(32, 3, Bn), 256, smem1>>>(x, theta_w, theta_b,
                                                     phi_w, phi_b, g_w, g_b);
    attn_mma_kernel<<<dim3(32, Bn), 256, smem2>>>();
    outconv_mma_kernel<<<dim3(32, 4, Bn), 256, smem3>>>(x, out_w, out_b, gamma, out);
}

// round 4
// speedup vs baseline: 4.5519x; 1.6616x over previous
#include <cuda_runtime.h>
#include <cstddef>
#include <cstdint>

#define Bn 8
#define Cc 256
#define Nn 4096      // 64*64 spatial
#define Mm 1024      // 32*32 pooled
#define Dd 32
#define Dv 128

// Scratch (device globals; no allocations allowed)
__device__ float g_theta[Bn * Nn * Dd];   // (n, i, d)
__device__ float g_phi[Bn * Dd * Mm];     // (n, d, j)
__device__ float g_gp [Bn * Dv * Mm];     // (n, v, j)
__device__ float g_att[Bn * Nn * Dv];     // (n, i, v)

__device__ __forceinline__ void mma_tf32(float c[4], const uint32_t a[4],
                                         uint32_t b0, uint32_t b1) {
    asm volatile("mma.sync.aligned.m16n8k8.row.col.f32.tf32.tf32.f32 "
        "{%0,%1,%2,%3}, {%4,%5,%6,%7}, {%8,%9}, {%0,%1,%2,%3};"
        : "+f"(c[0]), "+f"(c[1]), "+f"(c[2]), "+f"(c[3])
        : "r"(a[0]), "r"(a[1]), "r"(a[2]), "r"(a[3]), "r"(b0), "r"(b1));
}
__device__ __forceinline__ void cp16(void* dst_smem, const void* src) {
    uint32_t d = (uint32_t)__cvta_generic_to_shared(dst_smem);
    asm volatile("cp.async.cg.shared.global [%0], [%1], 16;\n" :: "r"(d), "l"(src));
}
__device__ __forceinline__ void cp_commit() {
    asm volatile("cp.async.commit_group;\n");
}
template<int N> __device__ __forceinline__ void cp_wait() {
    asm volatile("cp.async.wait_group %0;\n" :: "n"(N));
}

// ---------------------------------------------------------------------------
// Kernel 1: fused projections + maxpool, tf32 MMA, cp.async double-buffered.
// grid (32 i-tiles, 3 groups, 8 batches), 256 threads = 8 warps (4 m x 2 n).
// ---------------------------------------------------------------------------
#define WS  36    // weight smem stride (A frag banks 4*gq+tq, conflict-free)
#define XSS 136   // X smem stride      (B frag banks 8*tq+gq, conflict-free)
#define YSS 132

__global__ void __launch_bounds__(256) proj_mma_kernel(
    const float* __restrict__ x,
    const float* __restrict__ theta_w, const float* __restrict__ theta_b,
    const float* __restrict__ phi_w,   const float* __restrict__ phi_b,
    const float* __restrict__ g_w,     const float* __restrict__ g_b)
{
    extern __shared__ float sm[];
    float* Ws = sm;                    // 2 x 64 x 36
    float* Xs = sm + 2 * 64 * WS;      // 2 x 32 x 136
    float* Ys = Xs + 2 * 32 * XSS;     // 64 x 132

    const int bi  = blockIdx.x;
    const int grp = blockIdx.y;
    const int n   = blockIdx.z;
    const int t   = threadIdx.x;
    const int w   = t >> 5, lane = t & 31;
    const int gq  = lane >> 2, tq = lane & 3;
    const int mrow = (w & 3) * 16;
    const int nc0  = (w >> 2) * 64;
    const int base = bi * 128;

    const float* xb = x + (size_t)n * Cc * Nn;

    // issue async loads for K-chunk kc into buffer buf
    auto issue = [&](int kc, int buf) {
        float* Wb = Ws + buf * 64 * WS;
        float* Xb = Xs + buf * 32 * XSS;
#pragma unroll
        for (int it = 0; it < 2; it++) {
            int idx = t + it * 256;             // 512 chunks of 16B (W: 64x32)
            int r = idx >> 3, kq = (idx & 7) * 4;
            const float* src;
            if (grp == 0) src = (r < 32) ? &theta_w[r * Cc + kc + kq]
                                         : &phi_w[(r - 32) * Cc + kc + kq];
            else          src = &g_w[((grp - 1) * 64 + r) * Cc + kc + kq];
            cp16(&Wb[r * WS + kq], src);
        }
#pragma unroll
        for (int it = 0; it < 4; it++) {
            int idx = t + it * 256;             // 1024 chunks (X: 32x128)
            int k = idx >> 5, i4 = (idx & 31) * 4;
            cp16(&Xb[k * XSS + i4], &xb[(size_t)(kc + k) * Nn + base + i4]);
        }
        cp_commit();
    };

    float acc[8][4];
#pragma unroll
    for (int nt = 0; nt < 8; nt++)
#pragma unroll
        for (int c = 0; c < 4; c++) acc[nt][c] = 0.f;

    issue(0, 0);
    for (int c8 = 0; c8 < 8; c8++) {
        if (c8 < 7) { issue((c8 + 1) * 32, (c8 + 1) & 1); cp_wait<1>(); }
        else        { cp_wait<0>(); }
        __syncthreads();
        const float* Wb = Ws + (c8 & 1) * 64 * WS;
        const float* Xb = Xs + (c8 & 1) * 32 * XSS;
#pragma unroll
        for (int ks = 0; ks < 4; ks++) {
            uint32_t a[4];
            a[0] = __float_as_uint(Wb[(mrow + gq    ) * WS + ks * 8 + tq    ]);
            a[1] = __float_as_uint(Wb[(mrow + gq + 8) * WS + ks * 8 + tq    ]);
            a[2] = __float_as_uint(Wb[(mrow + gq    ) * WS + ks * 8 + tq + 4]);
            a[3] = __float_as_uint(Wb[(mrow + gq + 8) * WS + ks * 8 + tq + 4]);
#pragma unroll
            for (int nt = 0; nt < 8; nt++) {
                uint32_t b0 = __float_as_uint(Xb[(ks * 8 + tq    ) * XSS + nc0 + nt * 8 + gq]);
                uint32_t b1 = __float_as_uint(Xb[(ks * 8 + tq + 4) * XSS + nc0 + nt * 8 + gq]);
                mma_tf32(acc[nt], a, b0, b1);
            }
        }
        __syncthreads();
    }

    // stage to Ys with bias
    {
        int r0 = mrow + gq, r1 = mrow + gq + 8;
        float b0, b1;
        if (grp == 0) {
            b0 = (r0 < 32) ? theta_b[r0] : phi_b[r0 - 32];
            b1 = (r1 < 32) ? theta_b[r1] : phi_b[r1 - 32];
        } else {
            b0 = g_b[(grp - 1) * 64 + r0];
            b1 = g_b[(grp - 1) * 64 + r1];
        }
#pragma unroll
        for (int nt = 0; nt < 8; nt++) {
            int col = nc0 + nt * 8 + tq * 2;
            *(float2*)&Ys[r0 * YSS + col] = make_float2(acc[nt][0] + b0, acc[nt][1] + b0);
            *(float2*)&Ys[r1 * YSS + col] = make_float2(acc[nt][2] + b1, acc[nt][3] + b1);
        }
    }
    __syncthreads();

    if (grp == 0) {
        for (int idx = t; idx < 32 * 128; idx += 256) {
            int o = idx & 31, i = idx >> 5;
            g_theta[((size_t)n * Nn + base + i) * Dd + o] = Ys[o * YSS + i];
        }
        for (int idx = t; idx < 32 * 32; idx += 256) {
            int o = idx >> 5, jw = idx & 31;
            const float* yr = &Ys[(32 + o) * YSS];
            float m0 = fmaxf(yr[2 * jw],      yr[2 * jw + 1]);
            float m1 = fmaxf(yr[64 + 2 * jw], yr[64 + 2 * jw + 1]);
            g_phi[((size_t)n * Dd + o) * Mm + bi * 32 + jw] = fmaxf(m0, m1);
        }
    } else {
        int vbase = (grp - 1) * 64;
        for (int idx = t; idx < 64 * 32; idx += 256) {
            int v = idx >> 5, jw = idx & 31;
            const float* yr = &Ys[v * YSS];
            float m0 = fmaxf(yr[2 * jw],      yr[2 * jw + 1]);
            float m1 = fmaxf(yr[64 + 2 * jw], yr[64 + 2 * jw + 1]);
            g_gp[((size_t)n * Dv + vbase + v) * Mm + bi * 32 + jw] = fmaxf(m0, m1);
        }
    }
}

// ---------------------------------------------------------------------------
// Kernel 2: flash attention, tf32 MMA, cp.async double-buffered,
// P redistributed E->A fragments via intra-quad shuffles (no smem round-trip).
// grid (32 q-tiles, 8 batches), 256 threads = 8 warps x 16 query rows.
// ---------------------------------------------------------------------------
#define KB  64
#define PHS 72   // phi stride: B banks 8*tq+gq conflict-free
#define GSS 68   // g   stride: B banks 4*gq+tq conflict-free

__global__ void __launch_bounds__(256) attn_mma_kernel()
{
    extern __shared__ float sm[];
    float* Phs = sm;                     // 2 x 32 x 72
    float* Gs  = sm + 2 * Dd * PHS;      // 2 x 128 x 68

    const int n  = blockIdx.y;
    const int i0 = blockIdx.x * 128;
    const int t  = threadIdx.x;
    const int w  = t >> 5;
    const int lane = t & 31;
    const int qb = w * 16;
    const int gq = lane >> 2;
    const int tq = lane & 3;

    // Q A-fragments (persist): raw fp32 bits, HW truncates to tf32
    uint32_t qa[4][4];
    {
        const float* th = g_theta + ((size_t)n * Nn + i0 + qb) * Dd;
#pragma unroll
        for (int kc = 0; kc < 4; kc++) {
            qa[kc][0] = __float_as_uint(th[(gq    ) * Dd + kc * 8 + tq    ]);
            qa[kc][1] = __float_as_uint(th[(gq + 8) * Dd + kc * 8 + tq    ]);
            qa[kc][2] = __float_as_uint(th[(gq    ) * Dd + kc * 8 + tq + 4]);
            qa[kc][3] = __float_as_uint(th[(gq + 8) * Dd + kc * 8 + tq + 4]);
        }
    }

    auto issue = [&](int jb, int buf) {
        float* Pb = Phs + buf * Dd * PHS;
        float* Gb = Gs  + buf * Dv * GSS;
#pragma unroll
        for (int it = 0; it < 2; it++) {
            int idx = t + it * 256;                  // phi: 32x64 -> 512 cp
            int d = idx >> 4, j4 = (idx & 15) * 4;
            cp16(&Pb[d * PHS + j4], &g_phi[((size_t)n * Dd + d) * Mm + jb + j4]);
        }
#pragma unroll
        for (int it = 0; it < 8; it++) {
            int idx = t + it * 256;                  // g: 128x64 -> 2048 cp
            int vv = idx >> 4, j4 = (idx & 15) * 4;
            cp16(&Gb[vv * GSS + j4], &g_gp[((size_t)n * Dv + vv) * Mm + jb + j4]);
        }
        cp_commit();
    };

    float oacc[16][4];
#pragma unroll
    for (int vt = 0; vt < 16; vt++)
#pragma unroll
        for (int c = 0; c < 4; c++) oacc[vt][c] = 0.f;

    float m0 = -1e30f, m1 = -1e30f, l0 = 0.f, l1 = 0.f;

    issue(0, 0);
    for (int kb = 0; kb < Mm / KB; kb++) {
        if (kb < Mm / KB - 1) { issue((kb + 1) * KB, (kb + 1) & 1); cp_wait<1>(); }
        else                  { cp_wait<0>(); }
        __syncthreads();
        const float* Pb = Phs + (kb & 1) * Dd * PHS;
        const float* Gb = Gs  + (kb & 1) * Dv * GSS;

        // ---- energy: E[16q x 64k] per warp ----
        float e[8][4];
#pragma unroll
        for (int nt = 0; nt < 8; nt++)
#pragma unroll
            for (int c = 0; c < 4; c++) e[nt][c] = 0.f;
#pragma unroll
        for (int kc = 0; kc < 4; kc++)
#pragma unroll
            for (int nt = 0; nt < 8; nt++) {
                uint32_t b0 = __float_as_uint(Pb[(kc * 8 + tq    ) * PHS + nt * 8 + gq]);
                uint32_t b1 = __float_as_uint(Pb[(kc * 8 + tq + 4) * PHS + nt * 8 + gq]);
                mma_tf32(e[nt], qa[kc], b0, b1);
            }

        // ---- online softmax (rows gq, gq+8) ----
        float rm0 = m0, rm1 = m1;
#pragma unroll
        for (int nt = 0; nt < 8; nt++) {
            rm0 = fmaxf(rm0, fmaxf(e[nt][0], e[nt][1]));
            rm1 = fmaxf(rm1, fmaxf(e[nt][2], e[nt][3]));
        }
        rm0 = fmaxf(rm0, __shfl_xor_sync(0xffffffff, rm0, 1));
        rm0 = fmaxf(rm0, __shfl_xor_sync(0xffffffff, rm0, 2));
        rm1 = fmaxf(rm1, __shfl_xor_sync(0xffffffff, rm1, 1));
        rm1 = fmaxf(rm1, __shfl_xor_sync(0xffffffff, rm1, 2));
        float sc0 = __expf(m0 - rm0);
        float sc1 = __expf(m1 - rm1);
        m0 = rm0; m1 = rm1;

        float s0 = 0.f, s1 = 0.f;
#pragma unroll
        for (int nt = 0; nt < 8; nt++) {
            e[nt][0] = __expf(e[nt][0] - rm0);
            e[nt][1] = __expf(e[nt][1] - rm0);
            e[nt][2] = __expf(e[nt][2] - rm1);
            e[nt][3] = __expf(e[nt][3] - rm1);
            s0 += e[nt][0] + e[nt][1];
            s1 += e[nt][2] + e[nt][3];
        }
        s0 += __shfl_xor_sync(0xffffffff, s0, 1);
        s0 += __shfl_xor_sync(0xffffffff, s0, 2);
        s1 += __shfl_xor_sync(0xffffffff, s1, 1);
        s1 += __shfl_xor_sync(0xffffffff, s1, 2);
        l0 = l0 * sc0 + s0;
        l1 = l1 * sc1 + s1;

#pragma unroll
        for (int vt = 0; vt < 16; vt++) {
            oacc[vt][0] *= sc0; oacc[vt][1] *= sc0;
            oacc[vt][2] *= sc1; oacc[vt][3] *= sc1;
        }

        // ---- P.V: build A-frags from E C-frags via quad shuffles ----
        const int parity = tq & 1;
        const int s_lo = tq >> 1;
#pragma unroll
        for (int kc = 0; kc < 8; kc++) {
            float v0 = __shfl_sync(0xffffffff, e[kc][0], s_lo,     4);
            float v1 = __shfl_sync(0xffffffff, e[kc][1], s_lo,     4);
            float v2 = __shfl_sync(0xffffffff, e[kc][2], s_lo,     4);
            float v3 = __shfl_sync(0xffffffff, e[kc][3], s_lo,     4);
            float w0 = __shfl_sync(0xffffffff, e[kc][0], s_lo + 2, 4);
            float w1 = __shfl_sync(0xffffffff, e[kc][1], s_lo + 2, 4);
            float w2 = __shfl_sync(0xffffffff, e[kc][2], s_lo + 2, 4);
            float w3 = __shfl_sync(0xffffffff, e[kc][3], s_lo + 2, 4);
            uint32_t pa[4];
            pa[0] = __float_as_uint(parity ? v1 : v0);
            pa[1] = __float_as_uint(parity ? v3 : v2);
            pa[2] = __float_as_uint(parity ? w1 : w0);
            pa[3] = __float_as_uint(parity ? w3 : w2);
#pragma unroll
            for (int vt = 0; vt < 16; vt++) {
                uint32_t b0 = __float_as_uint(Gb[(vt * 8 + gq) * GSS + kc * 8 + tq    ]);
                uint32_t b1 = __float_as_uint(Gb[(vt * 8 + gq) * GSS + kc * 8 + tq + 4]);
                mma_tf32(oacc[vt], pa, b0, b1);
            }
        }
        __syncthreads();
    }

    // ---- epilogue: normalize and store (n, i, v) ----
    const float inv0 = 1.f / l0;
    const float inv1 = 1.f / l1;
    float* outp0 = g_att + ((size_t)n * Nn + i0 + qb + gq    ) * Dv;
    float* outp1 = g_att + ((size_t)n * Nn + i0 + qb + gq + 8) * Dv;
#pragma unroll
    for (int vt = 0; vt < 16; vt++) {
        *(float2*)&outp0[vt * 8 + tq * 2] = make_float2(oacc[vt][0] * inv0, oacc[vt][1] * inv0);
        *(float2*)&outp1[vt * 8 + tq * 2] = make_float2(oacc[vt][2] * inv1, oacc[vt][3] * inv1);
    }
}

// ---------------------------------------------------------------------------
// Kernel 3: output 1x1 conv + residual, tf32 MMA, NO transpose:
// att's natural [i][v] layout serves directly as the col-major B operand.
// grid (32 i-blocks, 4 c-blocks, 8 batches), 256 threads = 8 warps (4m x 2n).
// ---------------------------------------------------------------------------
#define ASS 132   // att smem stride [i][v]: B banks 4*gq+tq conflict-free
#define OWS 132   // weight smem stride:     A banks 4*gq+tq conflict-free

__global__ void __launch_bounds__(256) outconv_mma_kernel(
    const float* __restrict__ x,
    const float* __restrict__ out_w,
    const float* __restrict__ out_b,
    const float* __restrict__ gamma,
    float* __restrict__ out)
{
    extern __shared__ float sm[];
    float* As  = sm;               // 128 i x 132 (v)
    float* Wsm = As + 128 * ASS;   // 64 c x 132 (v)

    const int ib = blockIdx.x, cb = blockIdx.y, n = blockIdx.z;
    const int t = threadIdx.x;
    const int w = t >> 5, lane = t & 31;
    const int gq = lane >> 2, tq = lane & 3;
    const int mrow = (w & 3) * 16;
    const int nc0  = (w >> 2) * 64;
    const int ibase = ib * 128, cbase = cb * 64;

    // att tile: coalesced float4 in, float4 out, same layout (no transpose)
#pragma unroll
    for (int it = 0; it < 16; it++) {
        int idx = t + it * 256;              // 4096 float4: 128 i x 32
        int i = idx >> 5, v4 = (idx & 31) * 4;
        float4 a = *(const float4*)&g_att[((size_t)n * Nn + ibase + i) * Dv + v4];
        *(float4*)&As[i * ASS + v4] = a;
    }
#pragma unroll
    for (int it = 0; it < 8; it++) {
        int idx = t + it * 256;              // 2048 float4: 64 c x 32
        int r = idx >> 5, v4 = (idx & 31) * 4;
        float4 wv = *(const float4*)&out_w[(size_t)(cbase + r) * Dv + v4];
        *(float4*)&Wsm[r * OWS + v4] = wv;
    }
    __syncthreads();

    float acc[8][4];
#pragma unroll
    for (int nt = 0; nt < 8; nt++)
#pragma unroll
        for (int c = 0; c < 4; c++) acc[nt][c] = 0.f;

#pragma unroll
    for (int kc = 0; kc < 16; kc++) {
        uint32_t a[4];
        a[0] = __float_as_uint(Wsm[(mrow + gq    ) * OWS + kc * 8 + tq    ]);
        a[1] = __float_as_uint(Wsm[(mrow + gq + 8) * OWS + kc * 8 + tq    ]);
        a[2] = __float_as_uint(Wsm[(mrow + gq    ) * OWS + kc * 8 + tq + 4]);
        a[3] = __float_as_uint(Wsm[(mrow + gq + 8) * OWS + kc * 8 + tq + 4]);
#pragma unroll
        for (int nt = 0; nt < 8; nt++) {
            uint32_t b0 = __float_as_uint(As[(nc0 + nt * 8 + gq) * ASS + kc * 8 + tq    ]);
            uint32_t b1 = __float_as_uint(As[(nc0 + nt * 8 + gq) * ASS + kc * 8 + tq + 4]);
            mma_tf32(acc[nt], a, b0, b1);
        }
    }

    const float gm = gamma[0];
    const int c0 = cbase + mrow + gq;
    const int c1 = c0 + 8;
    const float b0 = out_b[c0], b1 = out_b[c1];
#pragma unroll
    for (int nt = 0; nt < 8; nt++) {
        int col = ibase + nc0 + nt * 8 + tq * 2;
        size_t off0 = ((size_t)n * Cc + c0) * Nn + col;
        size_t off1 = ((size_t)n * Cc + c1) * Nn + col;
        float2 xv0 = *(const float2*)&x[off0];
        float2 xv1 = *(const float2*)&x[off1];
        float2 o0, o1;
        o0.x = gm * (acc[nt][0] + b0) + xv0.x;
        o0.y = gm * (acc[nt][1] + b0) + xv0.y;
        o1.x = gm * (acc[nt][2] + b1) + xv1.x;
        o1.y = gm * (acc[nt][3] + b1) + xv1.y;
        *(float2*)&out[off0] = o0;
        *(float2*)&out[off1] = o1;
    }
}

// ---------------------------------------------------------------------------
extern "C" void kernel_launch(void* const* d_in, const int* in_sizes, int n_in,
                              void* d_out, int out_size)
{
    const float* x       = (const float*)d_in[0];
    const float* theta_w = (const float*)d_in[1];
    const float* theta_b = (const float*)d_in[2];
    const float* phi_w   = (const float*)d_in[3];
    const float* phi_b   = (const float*)d_in[4];
    const float* g_w     = (const float*)d_in[5];
    const float* g_b     = (const float*)d_in[6];
    const float* out_w   = (const float*)d_in[7];
    const float* out_b   = (const float*)d_in[8];
    const float* gamma   = (const float*)d_in[9];
    float* out = (float*)d_out;

    const int smem1 = (2 * 64 * WS + 2 * 32 * XSS + 64 * YSS) * 4;   // ~85 KB
    const int smem2 = (2 * Dd * PHS + 2 * Dv * GSS) * 4;             // ~86 KB
    const int smem3 = (128 * ASS + 64 * OWS) * 4;                    // ~99 KB

    cudaFuncSetAttribute(proj_mma_kernel,    cudaFuncAttributeMaxDynamicSharedMemorySize, smem1);
    cudaFuncSetAttribute(attn_mma_kernel,    cudaFuncAttributeMaxDynamicSharedMemorySize, smem2);
    cudaFuncSetAttribute(outconv_mma_kernel, cudaFuncAttributeMaxDynamicSharedMemorySize, smem3);

    proj_mma_kernel<<<dim3(32, 3, Bn), 256, smem1>>>(x, theta_w, theta_b,
                                                     phi_w, phi_b, g_w, g_b);
    attn_mma_kernel<<<dim3(32, Bn), 256, smem2>>>();
    outconv_mma_kernel<<<dim3(32, 4, Bn), 256, smem3>>>(x, out_w, out_b, gamma, out);
}